// round 17
// baseline (speedup 1.0000x reference)
#include <cuda_runtime.h>
#include <math.h>
#include <stdint.h>

// Problem constants
#define Bc    2
#define Sc    2048
#define Ec    2048
#define Hc    16
#define HDc   128
#define Mrows 4096     // B*S
#define QKV_N 6144     // 3*E
#define GK    2048     // K dim of both GEMMs

// Scratch (device globals: allocation-free per harness rules)
__device__ float g_qkv[(size_t)Mrows * QKV_N];   // ~100 MB
__device__ float g_attn[(size_t)Mrows * Ec];     // ~33 MB

// ---------------------------------------------------------------------------
// Helpers
// ---------------------------------------------------------------------------
__device__ __forceinline__ uint32_t f2tf32(float x) {
    uint32_t r;
    asm("cvt.rna.tf32.f32 %0, %1;" : "=r"(r) : "f"(x));
    return r;
}
__device__ __forceinline__ void mma8(float* c,
                                     uint32_t a0, uint32_t a1, uint32_t a2, uint32_t a3,
                                     uint32_t b0, uint32_t b1) {
    asm volatile(
        "mma.sync.aligned.m16n8k8.row.col.f32.tf32.tf32.f32 "
        "{%0,%1,%2,%3}, {%4,%5,%6,%7}, {%8,%9}, {%0,%1,%2,%3};"
        : "+f"(c[0]), "+f"(c[1]), "+f"(c[2]), "+f"(c[3])
        : "r"(a0), "r"(a1), "r"(a2), "r"(a3), "r"(b0), "r"(b1));
}

// ---------------------------------------------------------------------------
// Adaptive-precision TF32 GEMM (R15/R16 passing version, unchanged)
// C[M,N] = A[M,K] @ B[N,K]^T + bias[N]
//   vmode 0 (qkv): q/k tiles (bx%3!=2) -> 3 terms; v tiles -> 1 term
//   vmode 1 (proj): all tiles 1 term
// ---------------------------------------------------------------------------
#define BKg 32
#define SPAD 36

__global__ __launch_bounds__(256)
void gemm_tf32x3(const float* __restrict__ A,
                 const float* __restrict__ Bw,
                 const float* __restrict__ bias,
                 float* __restrict__ C,
                 int Ndim, int vmode)
{
    extern __shared__ uint2 sm2[];
    uint2* As = sm2;
    uint2* Bs = sm2 + 128 * SPAD;

    const int tid   = threadIdx.x;
    const int lane  = tid & 31;
    const int wid   = tid >> 5;
    const int m_off = (wid & 1) << 6;
    const int n_off = (wid >> 1) << 5;
    const int bm    = blockIdx.y << 7;
    const int bn    = blockIdx.x << 7;

    const int terms = (vmode == 0) ? (((blockIdx.x % 3) != 2) ? 3 : 1) : 1;
    const bool need_alo = (terms == 3);
    const bool need_blo = (terms >= 2);

    const int row_base = tid >> 3;
    const int col4     = (tid & 7) << 2;

    float c[4][4][4];
#pragma unroll
    for (int mt = 0; mt < 4; mt++)
#pragma unroll
        for (int nt = 0; nt < 4; nt++)
#pragma unroll
            for (int e = 0; e < 4; e++) c[mt][nt][e] = 0.f;

    float4 pa[4], pb[4];
#pragma unroll
    for (int i = 0; i < 4; i++) {
        int r = row_base + 32 * i;
        pa[i] = *(const float4*)&A [(size_t)(bm + r) * GK + col4];
        pb[i] = *(const float4*)&Bw[(size_t)(bn + r) * GK + col4];
    }

    const int nsteps = GK / BKg;
    for (int step = 0; step < nsteps; step++) {
        __syncthreads();
#pragma unroll
        for (int i = 0; i < 4; i++) {
            int r = row_base + 32 * i;
            float av[4] = {pa[i].x, pa[i].y, pa[i].z, pa[i].w};
            float bv[4] = {pb[i].x, pb[i].y, pb[i].z, pb[i].w};
            uint32_t ah[4], al[4], bh[4], bl[4];
#pragma unroll
            for (int j = 0; j < 4; j++) {
                ah[j] = f2tf32(av[j]);
                al[j] = need_alo ? f2tf32(av[j] - __uint_as_float(ah[j])) : 0u;
                bh[j] = f2tf32(bv[j]);
                bl[j] = need_blo ? f2tf32(bv[j] - __uint_as_float(bh[j])) : 0u;
            }
            *(uint4*)&As[r * SPAD + col4    ] = make_uint4(ah[0], al[0], ah[1], al[1]);
            *(uint4*)&As[r * SPAD + col4 + 2] = make_uint4(ah[2], al[2], ah[3], al[3]);
            *(uint4*)&Bs[r * SPAD + col4    ] = make_uint4(bh[0], bl[0], bh[1], bl[1]);
            *(uint4*)&Bs[r * SPAD + col4 + 2] = make_uint4(bh[2], bl[2], bh[3], bl[3]);
        }
        __syncthreads();

        if (step + 1 < nsteps) {
            int k0 = (step + 1) * BKg;
#pragma unroll
            for (int i = 0; i < 4; i++) {
                int r = row_base + 32 * i;
                pa[i] = *(const float4*)&A [(size_t)(bm + r) * GK + k0 + col4];
                pb[i] = *(const float4*)&Bw[(size_t)(bn + r) * GK + k0 + col4];
            }
        }

#pragma unroll
        for (int kk = 0; kk < 4; kk++) {
            const int kc = (kk << 3) + (lane & 3);
            uint2 a[4][4];
#pragma unroll
            for (int mt = 0; mt < 4; mt++) {
                int r0 = m_off + mt * 16 + (lane >> 2);
                a[mt][0] = As[r0 * SPAD + kc];
                a[mt][1] = As[(r0 + 8) * SPAD + kc];
                a[mt][2] = As[r0 * SPAD + kc + 4];
                a[mt][3] = As[(r0 + 8) * SPAD + kc + 4];
            }
            uint2 b[4][2];
#pragma unroll
            for (int nt = 0; nt < 4; nt++) {
                int n0 = n_off + nt * 8 + (lane >> 2);
                b[nt][0] = Bs[n0 * SPAD + kc];
                b[nt][1] = Bs[n0 * SPAD + kc + 4];
            }
#pragma unroll
            for (int mt = 0; mt < 4; mt++)
#pragma unroll
                for (int nt = 0; nt < 4; nt++)
                    mma8(c[mt][nt], a[mt][0].x, a[mt][1].x, a[mt][2].x, a[mt][3].x,
                                    b[nt][0].x, b[nt][1].x);
            if (terms >= 2) {
#pragma unroll
                for (int mt = 0; mt < 4; mt++)
#pragma unroll
                    for (int nt = 0; nt < 4; nt++)
                        mma8(c[mt][nt], a[mt][0].x, a[mt][1].x, a[mt][2].x, a[mt][3].x,
                                        b[nt][0].y, b[nt][1].y);
            }
            if (terms == 3) {
#pragma unroll
                for (int mt = 0; mt < 4; mt++)
#pragma unroll
                    for (int nt = 0; nt < 4; nt++)
                        mma8(c[mt][nt], a[mt][0].y, a[mt][1].y, a[mt][2].y, a[mt][3].y,
                                        b[nt][0].x, b[nt][1].x);
            }
        }
    }

#pragma unroll
    for (int mt = 0; mt < 4; mt++) {
        int r0 = bm + m_off + mt * 16 + (lane >> 2);
#pragma unroll
        for (int nt = 0; nt < 4; nt++) {
            int col = bn + n_off + nt * 8 + ((lane & 3) << 1);
            float b0 = bias[col], b1 = bias[col + 1];
            *(float2*)&C[(size_t)r0 * Ndim + col] =
                make_float2(c[mt][nt][0] + b0, c[mt][nt][1] + b1);
            *(float2*)&C[(size_t)(r0 + 8) * Ndim + col] =
                make_float2(c[mt][nt][2] + b0, c[mt][nt][3] + b1);
        }
    }
}

// ---------------------------------------------------------------------------
// Flash attention v7: fp32 SIMT, 64-q tiles, 512 threads, 2 CTAs/SM.
// In-register online softmax (rows 2ty+i). Smem 115712 B:
//   Qs 64x128 (stride 128 — row-broadcast reads, no padding needed)
//   Ks 64x132 (stride 132 — column-indexed reads need padding)
//   Vs 64x128 (stride 128 — row-uniform reads)
//   Ps 64x64
// ---------------------------------------------------------------------------
#define SQ7 64
#define SK7 64
#define QST7 128
#define KST7 132
#define VST7 128
#define FL7_SMEM ((SQ7*QST7 + SK7*KST7 + SK7*VST7 + SQ7*SK7) * 4)

__global__ __launch_bounds__(512, 2)
void flash_v7()
{
    extern __shared__ float smf[];
    float* Qs = smf;                       // 64*128
    float* Ks = Qs + SQ7*QST7;             // 64*132
    float* Vs = Ks + SK7*KST7;             // 64*128
    float* Ps = Vs + SK7*VST7;             // 64*64

    const int tid = threadIdx.x;
    const int ty  = tid >> 4, tx = tid & 15;    // 32 x 16
    const int b = blockIdx.z, h = blockIdx.y;
    const int q0 = blockIdx.x << 6;

    const size_t qbase = ((size_t)(b*Sc + q0)) * QKV_N + h*384;
    const float scale = 11.3137084989847604f;  // HD**0.5 (reference MULTIPLIES)

    // Load Q tile (64 x 128), scale folded in: 2048 float4 / 512 thr = 4 each
#pragma unroll
    for (int i = 0; i < 4; i++) {
        int idx = tid + (i << 9);
        int r   = idx >> 5;
        int c4  = (idx & 31) << 2;
        float4 v = *(const float4*)&g_qkv[qbase + (size_t)r*QKV_N + c4];
        v.x *= scale; v.y *= scale; v.z *= scale; v.w *= scale;
        *(float4*)&Qs[r*QST7 + c4] = v;
    }

    float m_r[2], l_r[2];
#pragma unroll
    for (int i = 0; i < 2; i++) { m_r[i] = -1e30f; l_r[i] = 0.f; }

    float o[2][8];
#pragma unroll
    for (int i = 0; i < 2; i++)
#pragma unroll
        for (int c = 0; c < 8; c++) o[i][c] = 0.f;

    for (int kt = 0; kt < Sc; kt += SK7) {
        __syncthreads();   // Ks/Vs free (prev PV done); covers Q load on iter 0
        const size_t kbase = ((size_t)(b*Sc + kt)) * QKV_N + h*384;
#pragma unroll
        for (int i = 0; i < 4; i++) {
            int idx = tid + (i << 9);
            int r   = idx >> 5;
            int c4  = (idx & 31) << 2;
            *(float4*)&Ks[r*KST7 + c4] =
                *(const float4*)&g_qkv[kbase + (size_t)r*QKV_N + 128 + c4];
            *(float4*)&Vs[r*VST7 + c4] =
                *(const float4*)&g_qkv[kbase + (size_t)r*QKV_N + 256 + c4];
        }
        __syncthreads();

        // ---- S = Q @ K^T (rows 2ty+i, cols tx+16c) ----
        float s[2][4];
#pragma unroll
        for (int i = 0; i < 2; i++)
#pragma unroll
            for (int c = 0; c < 4; c++) s[i][c] = 0.f;

#pragma unroll 8
        for (int d = 0; d < HDc; d += 4) {
            float4 kf[4];
#pragma unroll
            for (int c = 0; c < 4; c++)
                kf[c] = *(const float4*)&Ks[(tx + 16*c)*KST7 + d];
#pragma unroll
            for (int i = 0; i < 2; i++) {
                float4 qf = *(const float4*)&Qs[(2*ty + i)*QST7 + d];
#pragma unroll
                for (int c = 0; c < 4; c++)
                    s[i][c] += qf.x*kf[c].x + qf.y*kf[c].y
                             + qf.z*kf[c].z + qf.w*kf[c].w;
            }
        }

        // ---- in-register online softmax (butterfly over 16 tx lanes) ----
        float alpha[2];
#pragma unroll
        for (int i = 0; i < 2; i++) {
            float mx = fmaxf(fmaxf(s[i][0], s[i][1]), fmaxf(s[i][2], s[i][3]));
#pragma unroll
            for (int off = 8; off > 0; off >>= 1)
                mx = fmaxf(mx, __shfl_xor_sync(0xffffffffu, mx, off));
            float mn = fmaxf(m_r[i], mx);
            float p0 = __expf(s[i][0] - mn);
            float p1 = __expf(s[i][1] - mn);
            float p2 = __expf(s[i][2] - mn);
            float p3 = __expf(s[i][3] - mn);
            s[i][0] = p0; s[i][1] = p1; s[i][2] = p2; s[i][3] = p3;
            float ps = (p0 + p1) + (p2 + p3);
#pragma unroll
            for (int off = 8; off > 0; off >>= 1)
                ps += __shfl_xor_sync(0xffffffffu, ps, off);
            alpha[i] = __expf(m_r[i] - mn);
            l_r[i] = l_r[i] * alpha[i] + ps;
            m_r[i] = mn;
        }

        // probabilities to smem, consumed by the SAME warp
#pragma unroll
        for (int i = 0; i < 2; i++)
#pragma unroll
            for (int c = 0; c < 4; c++)
                Ps[(2*ty + i)*SK7 + tx + 16*c] = s[i][c];
        __syncwarp();

        // ---- O = O*alpha + P @ V ----
#pragma unroll
        for (int i = 0; i < 2; i++)
#pragma unroll
            for (int c = 0; c < 8; c++) o[i][c] *= alpha[i];

#pragma unroll 4
        for (int j = 0; j < SK7; j++) {
            float p[2], v[8];
#pragma unroll
            for (int i = 0; i < 2; i++) p[i] = Ps[(2*ty + i)*SK7 + j];
#pragma unroll
            for (int c = 0; c < 8; c++) v[c] = Vs[j*VST7 + tx + 16*c];
#pragma unroll
            for (int i = 0; i < 2; i++)
#pragma unroll
                for (int c = 0; c < 8; c++)
                    o[i][c] += p[i]*v[c];
        }
    }

    // Epilogue: normalize and scatter to (b, s, h*HD + d) layout
#pragma unroll
    for (int i = 0; i < 2; i++) {
        int r = 2*ty + i;
        float inv = 1.0f / l_r[i];
        size_t obase = ((size_t)(b*Sc + q0 + r)) * Ec + h*HDc;
#pragma unroll
        for (int c = 0; c < 8; c++)
            g_attn[obase + tx + 16*c] = o[i][c] * inv;
    }
}

// ---------------------------------------------------------------------------
extern "C" void kernel_launch(void* const* d_in, const int* in_sizes, int n_in,
                              void* d_out, int out_size)
{
    const float* query = (const float*)d_in[0];
    const float* Wqkv  = (const float*)d_in[3];
    const float* bqkv  = (const float*)d_in[4];
    const float* Wproj = (const float*)d_in[5];
    const float* bproj = (const float*)d_in[6];
    float* out = (float*)d_out;

    float *qkvp = nullptr, *attnp = nullptr;
    cudaGetSymbolAddress((void**)&qkvp,  g_qkv);
    cudaGetSymbolAddress((void**)&attnp, g_attn);

    const int gemm_smem = 2 * 128 * SPAD * (int)sizeof(uint2);  // 73728
    cudaFuncSetAttribute(gemm_tf32x3,
                         cudaFuncAttributeMaxDynamicSharedMemorySize, gemm_smem);

    // 1) qkv = query @ Wqkv^T + bqkv  (q/k tiles 3-term, v tiles 1-term)
    gemm_tf32x3<<<dim3(QKV_N/128, Mrows/128), 256, gemm_smem>>>(
        query, Wqkv, bqkv, qkvp, QKV_N, 0);

    // 2) flash attention v7 (64-q tiles, 2 CTAs/SM) -> g_attn
    cudaFuncSetAttribute(flash_v7,
                         cudaFuncAttributeMaxDynamicSharedMemorySize, FL7_SMEM);
    flash_v7<<<dim3(Sc/SQ7, Hc, Bc), 512, FL7_SMEM>>>();

    // 3) out = attn @ Wproj^T + bproj  (all tiles 1-term, linear path)
    gemm_tf32x3<<<dim3(Ec/128, Mrows/128), 256, gemm_smem>>>(
        attnp, Wproj, bproj, out, Ec, 1);
}